// round 3
// baseline (speedup 1.0000x reference)
#include <cuda_runtime.h>

#define IN_F   4096
#define OUT_F  4096
#define BATCH  16384
#define NSPLIT 32          // row-splits for W column-sum partials

// Scratch (no device allocation allowed) — all fully overwritten every
// launch sequence, so graph replays are deterministic.
__device__ float g_partial[NSPLIT * IN_F];   // 512 KB
__device__ float g_ws[IN_F];
__device__ float g_bsum;

// ---------------------------------------------------------------------------
// A1: partial column sums of W.
// tid -> (split, colgroup-of-4). Consecutive threads hit consecutive float4s
// within a row -> perfectly coalesced 16B/lane. Each thread walks
// OUT_F/NSPLIT = 128 rows. Total threads = NSPLIT * IN_F/4 = 32768.
// ---------------------------------------------------------------------------
__global__ void wsum_partial_kernel(const float4* __restrict__ W4) {
    const int colgs = IN_F / 4;                       // 1024
    int tid   = blockIdx.x * blockDim.x + threadIdx.x;
    int colg  = tid & (colgs - 1);
    int split = tid >> 10;                            // tid / 1024
    const int rows = OUT_F / NSPLIT;                  // 128
    const float4* p = W4 + (size_t)(split * rows) * colgs + colg;

    float4 acc = make_float4(0.f, 0.f, 0.f, 0.f);
    #pragma unroll 8
    for (int r = 0; r < rows; ++r) {
        float4 v = p[(size_t)r * colgs];
        acc.x += v.x; acc.y += v.y; acc.z += v.z; acc.w += v.w;
    }
    reinterpret_cast<float4*>(g_partial)[split * colgs + colg] = acc;
}

// ---------------------------------------------------------------------------
// A2: finalize ws[j] = sum over splits of partials. 4096 threads.
// ---------------------------------------------------------------------------
__global__ void wsum_finalize_kernel() {
    int j = blockIdx.x * blockDim.x + threadIdx.x;    // 0..IN_F-1
    float s = 0.f;
    #pragma unroll
    for (int k = 0; k < NSPLIT; ++k)
        s += g_partial[k * IN_F + j];
    g_ws[j] = s;
}

// ---------------------------------------------------------------------------
// A3: bias sum -> g_bsum. One block.
// ---------------------------------------------------------------------------
__global__ void bias_sum_kernel(const float* __restrict__ bias) {
    __shared__ float sh[32];
    float s = 0.f;
    for (int i = threadIdx.x; i < OUT_F; i += blockDim.x)
        s += bias[i];
    #pragma unroll
    for (int o = 16; o > 0; o >>= 1)
        s += __shfl_xor_sync(0xffffffffu, s, o);
    int lane = threadIdx.x & 31, warp = threadIdx.x >> 5;
    if (lane == 0) sh[warp] = s;
    __syncthreads();
    if (warp == 0) {
        float t = (lane < (int)(blockDim.x >> 5)) ? sh[lane] : 0.f;
        #pragma unroll
        for (int o = 16; o > 0; o >>= 1)
            t += __shfl_xor_sync(0xffffffffu, t, o);
        if (lane == 0) g_bsum = t;
    }
}

// ---------------------------------------------------------------------------
// B: out[row] = dot(x[row], ws) + bsum. One warp per row.
// Each lane: 32 float4 loads of x (coalesced across the warp) + 32 float4
// loads of ws (L1-resident after first warp). Fixed shuffle-reduce order
// -> bitwise deterministic.
// ---------------------------------------------------------------------------
__global__ void rowdot_kernel(const float4* __restrict__ x4,
                              float* __restrict__ out) {
    int gwarp = (blockIdx.x * blockDim.x + threadIdx.x) >> 5;
    int lane  = threadIdx.x & 31;
    if (gwarp >= BATCH) return;

    const int colgs = IN_F / 4;                        // 1024
    const float4* xr  = x4 + (size_t)gwarp * colgs;
    const float4* ws4 = reinterpret_cast<const float4*>(g_ws);

    float acc = 0.f;
    #pragma unroll 8
    for (int i = lane; i < colgs; i += 32) {
        float4 xv = xr[i];
        float4 wv = ws4[i];
        acc += xv.x * wv.x + xv.y * wv.y + xv.z * wv.z + xv.w * wv.w;
    }
    #pragma unroll
    for (int o = 16; o > 0; o >>= 1)
        acc += __shfl_xor_sync(0xffffffffu, acc, o);
    if (lane == 0)
        out[gwarp] = acc + g_bsum;
}

extern "C" void kernel_launch(void* const* d_in, const int* in_sizes, int n_in,
                              void* d_out, int out_size) {
    const float* x    = (const float*)d_in[0];   // [BATCH, IN_F]
    const float* W    = (const float*)d_in[1];   // [OUT_F, IN_F]
    const float* bias = (const float*)d_in[2];   // [OUT_F]
    float* out = (float*)d_out;                  // [BATCH, 1]

    (void)in_sizes; (void)n_in; (void)out_size;

    // A1: 32768 threads = 128 blocks x 256
    wsum_partial_kernel<<<(NSPLIT * (IN_F / 4)) / 256, 256>>>(
        reinterpret_cast<const float4*>(W));

    // A2: 4096 threads
    wsum_finalize_kernel<<<IN_F / 256, 256>>>();

    // A3: one block
    bias_sum_kernel<<<1, 1024>>>(bias);

    // B: one warp per row -> 16384 warps = 2048 blocks x 256 threads
    rowdot_kernel<<<(BATCH * 32) / 256, 256>>>(
        reinterpret_cast<const float4*>(x), out);
}

// round 4
// speedup vs baseline: 1.1120x; 1.1120x over previous
#include <cuda_runtime.h>

#define IN_F   4096
#define OUT_F  4096
#define BATCH  16384
#define NSPLIT 64          // row-splits for W column-sum partials

// Scratch (no device allocation allowed) — fully overwritten every launch
// sequence, so graph replays are deterministic.
__device__ float g_partial[NSPLIT * IN_F];   // 1 MB (L2-resident)
__device__ float g_ws[IN_F];
__device__ float g_bsum;

// ---------------------------------------------------------------------------
// A1: partial column sums of W.
// tid -> (split, colgroup-of-4). Consecutive threads hit consecutive float4s
// within a row -> perfectly coalesced. Each thread walks OUT_F/NSPLIT = 64
// rows. Total threads = NSPLIT * IN_F/4 = 65536 (256 blocks x 256).
// ---------------------------------------------------------------------------
__global__ __launch_bounds__(256)
void wsum_partial_kernel(const float4* __restrict__ W4) {
    const int colgs = IN_F / 4;                       // 1024
    int tid   = blockIdx.x * blockDim.x + threadIdx.x;
    int colg  = tid & (colgs - 1);
    int split = tid >> 10;                            // tid / 1024
    const int rows = OUT_F / NSPLIT;                  // 64
    const float4* p = W4 + (size_t)(split * rows) * colgs + colg;

    float4 acc = make_float4(0.f, 0.f, 0.f, 0.f);
    #pragma unroll 8
    for (int r = 0; r < rows; ++r) {
        float4 v = p[(size_t)r * colgs];
        acc.x += v.x; acc.y += v.y; acc.z += v.z; acc.w += v.w;
    }
    reinterpret_cast<float4*>(g_partial)[split * colgs + colg] = acc;
}

// ---------------------------------------------------------------------------
// A2 (fused): finalize ws[j] = sum over splits of partials (4096 threads),
// and block 0 additionally reduces bias -> g_bsum.
// Partials are L2-resident (1 MB), bias is 16 KB.
// ---------------------------------------------------------------------------
__global__ __launch_bounds__(512)
void wsum_finalize_bias_kernel(const float* __restrict__ bias) {
    int j = blockIdx.x * blockDim.x + threadIdx.x;    // 0..IN_F-1  (8 blocks x 512)
    float s = 0.f;
    #pragma unroll 16
    for (int k = 0; k < NSPLIT; ++k)
        s += g_partial[k * IN_F + j];
    g_ws[j] = s;

    // Block 0 also computes the bias sum.
    if (blockIdx.x == 0) {
        __shared__ float sh[16];
        float b = 0.f;
        for (int i = threadIdx.x; i < OUT_F; i += blockDim.x)
            b += __ldg(&bias[i]);
        #pragma unroll
        for (int o = 16; o > 0; o >>= 1)
            b += __shfl_xor_sync(0xffffffffu, b, o);
        int lane = threadIdx.x & 31, warp = threadIdx.x >> 5;
        if (lane == 0) sh[warp] = b;
        __syncthreads();
        if (warp == 0) {
            float t = (lane < (int)(blockDim.x >> 5)) ? sh[lane] : 0.f;
            #pragma unroll
            for (int o = 16; o > 0; o >>= 1)
                t += __shfl_xor_sync(0xffffffffu, t, o);
            if (lane == 0) g_bsum = t;
        }
    }
}

// ---------------------------------------------------------------------------
// B: out[row] = dot(x[row], ws) + bsum. One warp per row.
// Each lane: 32 float4 loads of x (coalesced across the warp) + 32 float4
// loads of ws (L1-resident after first pass). Fixed shuffle-reduce order
// -> bitwise deterministic.
// ---------------------------------------------------------------------------
__global__ __launch_bounds__(256)
void rowdot_kernel(const float4* __restrict__ x4,
                   float* __restrict__ out) {
    int gwarp = (blockIdx.x * blockDim.x + threadIdx.x) >> 5;
    int lane  = threadIdx.x & 31;
    if (gwarp >= BATCH) return;

    const int colgs = IN_F / 4;                        // 1024
    const float4* xr  = x4 + (size_t)gwarp * colgs;
    const float4* ws4 = reinterpret_cast<const float4*>(g_ws);

    float acc = 0.f;
    #pragma unroll 8
    for (int i = lane; i < colgs; i += 32) {
        float4 xv = xr[i];
        float4 wv = __ldg(&ws4[i]);
        acc += xv.x * wv.x + xv.y * wv.y + xv.z * wv.z + xv.w * wv.w;
    }
    #pragma unroll
    for (int o = 16; o > 0; o >>= 1)
        acc += __shfl_xor_sync(0xffffffffu, acc, o);
    if (lane == 0)
        out[gwarp] = acc + g_bsum;
}

extern "C" void kernel_launch(void* const* d_in, const int* in_sizes, int n_in,
                              void* d_out, int out_size) {
    const float* x    = (const float*)d_in[0];   // [BATCH, IN_F]
    const float* W    = (const float*)d_in[1];   // [OUT_F, IN_F]
    const float* bias = (const float*)d_in[2];   // [OUT_F]
    float* out = (float*)d_out;                  // [BATCH, 1]

    (void)in_sizes; (void)n_in; (void)out_size;

    // A1: 65536 threads = 256 blocks x 256
    wsum_partial_kernel<<<(NSPLIT * (IN_F / 4)) / 256, 256>>>(
        reinterpret_cast<const float4*>(W));

    // A2 fused with bias reduce: 4096 threads = 8 blocks x 512
    wsum_finalize_bias_kernel<<<IN_F / 512, 512>>>(bias);

    // B: one warp per row -> 16384 warps = 2048 blocks x 256 threads
    rowdot_kernel<<<(BATCH * 32) / 256, 256>>>(
        reinterpret_cast<const float4*>(x), out);
}